// round 10
// baseline (speedup 1.0000x reference)
#include <cuda_runtime.h>

#define NB 8
#define NX 256
#define NC 256
#define KSEG 4
#define KLEN 64   /* NX / KSEG */
#define KC 16     /* smem chunk depth */
#define NCH (KLEN / KC)

typedef unsigned long long u64;

// Split-K partial Gram matrices: [seg][b][c*NC+d]  (8 MB)
__device__ float g_G[KSEG * NB * NC * NC];
// Diagonal partials: [seg][b][c]  (32 KB)
__device__ float g_Sp[KSEG * NB * NC];

__device__ __forceinline__ u64 ffma2(u64 a, u64 b, u64 c) {
    u64 d;
    asm("fma.rn.f32x2 %0, %1, %2, %3;" : "=l"(d) : "l"(a), "l"(b), "l"(c));
    return d;
}
__device__ __forceinline__ u64 pack2(float x) {
    u64 d;
    unsigned xi = __float_as_uint(x);
    asm("mov.b64 %0, {%1, %1};" : "=l"(d) : "r"(xi));
    return d;
}
__device__ __forceinline__ float4 fuse4(float wa, float wp, float4 a, float4 p) {
    return make_float4(wa * a.x + wp * p.x, wa * a.y + wp * p.y,
                       wa * a.z + wp * p.z, wa * a.w + wp * p.w);
}

// ---------------------------------------------------------------------------
// K1: partial Gram  G[seg][b] += f[:,c]^T f[:,d] over k in [seg*64, ...+64)
//     f computed on the fly. 128x128 tile, 8x8 micro-tile, packed f32x2 FMAs.
//     KC=16 chunks, double-buffered smem: 1 sync per chunk.
//     grid = (16, 8): blockIdx.x = seg*4 + quad, blockIdx.y = b
// ---------------------------------------------------------------------------
__global__ __launch_bounds__(256) void k_gram(const float* __restrict__ amp,
                                              const float* __restrict__ ph,
                                              const float* __restrict__ wap,
                                              const float* __restrict__ wpp) {
    __shared__ __align__(16) float As[2][KC][128];
    __shared__ __align__(16) float Bs[2][KC][128];

    int b = blockIdx.y;
    int q = blockIdx.x & 3;
    int seg = blockIdx.x >> 2;
    int cBase = (q >> 1) * 128;
    int dBase = (q & 1) * 128;
    int tid = threadIdx.x;
    int tx = tid & 15;
    int ty = tid >> 4;
    int sr = tid >> 5;        // rows sr and sr+8
    int sc = (tid & 31) * 4;

    float wa = wap[0], wp = wpp[0];
    const float* ab = amp + b * NX * NC;
    const float* pb = ph + b * NX * NC;

    u64 acc[8][4];
#pragma unroll
    for (int i = 0; i < 8; i++)
#pragma unroll
        for (int j = 0; j < 4; j++) acc[i][j] = 0ull;

    int k0 = seg * KLEN;

    float4 ra0, rp0, rb0, rq0, ra1, rp1, rb1, rq1;

#define LOADCH(CH) do {                                                   \
    int kr = k0 + (CH) * KC + sr;                                         \
    ra0 = *(const float4*)(ab + kr * NC + cBase + sc);                    \
    rp0 = *(const float4*)(pb + kr * NC + cBase + sc);                    \
    rb0 = *(const float4*)(ab + kr * NC + dBase + sc);                    \
    rq0 = *(const float4*)(pb + kr * NC + dBase + sc);                    \
    ra1 = *(const float4*)(ab + (kr + 8) * NC + cBase + sc);              \
    rp1 = *(const float4*)(pb + (kr + 8) * NC + cBase + sc);              \
    rb1 = *(const float4*)(ab + (kr + 8) * NC + dBase + sc);              \
    rq1 = *(const float4*)(pb + (kr + 8) * NC + dBase + sc);              \
} while (0)

#define STORECH(BF) do {                                                  \
    *(float4*)&As[BF][sr][sc]     = fuse4(wa, wp, ra0, rp0);              \
    *(float4*)&As[BF][sr + 8][sc] = fuse4(wa, wp, ra1, rp1);              \
    *(float4*)&Bs[BF][sr][sc]     = fuse4(wa, wp, rb0, rq0);              \
    *(float4*)&Bs[BF][sr + 8][sc] = fuse4(wa, wp, rb1, rq1);              \
} while (0)

    LOADCH(0);
    STORECH(0);
    __syncthreads();

#pragma unroll 1
    for (int ch = 0; ch < NCH; ch++) {
        int bf = ch & 1;
        if (ch + 1 < NCH) LOADCH(ch + 1);

#pragma unroll
        for (int k = 0; k < KC; k++) {
            float4 a0 = *(const float4*)&As[bf][k][ty * 8];
            float4 a1 = *(const float4*)&As[bf][k][ty * 8 + 4];
            const u64* brow = (const u64*)&Bs[bf][k][tx * 8];
            u64 b2[4];
            b2[0] = brow[0]; b2[1] = brow[1]; b2[2] = brow[2]; b2[3] = brow[3];
            float av[8] = {a0.x, a0.y, a0.z, a0.w, a1.x, a1.y, a1.z, a1.w};
#pragma unroll
            for (int i = 0; i < 8; i++) {
                u64 ai = pack2(av[i]);
#pragma unroll
                for (int j = 0; j < 4; j++) acc[i][j] = ffma2(ai, b2[j], acc[i][j]);
            }
        }

        if (ch + 1 < NCH) {
            STORECH((ch + 1) & 1);
            __syncthreads();
        }
    }

    float* Gp = g_G + (size_t)(seg * NB + b) * NC * NC;
#pragma unroll
    for (int i = 0; i < 8; i++) {
        int c = cBase + ty * 8 + i;
        u64* dst = (u64*)(Gp + c * NC + dBase + tx * 8);
        dst[0] = acc[i][0]; dst[1] = acc[i][1]; dst[2] = acc[i][2]; dst[3] = acc[i][3];
    }

    if (cBase == dBase && tx == ty) {
        float* Sp = g_Sp + (seg * NB + b) * NC;
#pragma unroll
        for (int i = 0; i < 8; i++) {
            int c = cBase + ty * 8 + i;
            u64 v = acc[i][i >> 1];
            float f = (i & 1) ? __uint_as_float((unsigned)(v >> 32))
                              : __uint_as_float((unsigned)(v & 0xffffffffu));
            Sp[c] = f;
        }
    }
#undef LOADCH
#undef STORECH
}

// ---------------------------------------------------------------------------
// K2: grid = c (256), block = 512 = (d:256) x (half:2); thread handles
//     b = half*4 + it, it = 0..3. Full prefetch (16 G loads + 4 gumbel + S
//     staging) before a single sync; warp min + one cross-warp sync; hybrid
//     __logf fast path with precise-logf fallback inside a certainty margin
//     (decisions bit-identical to the precise version).
// ---------------------------------------------------------------------------
__global__ __launch_bounds__(512) void k_mask(const float* __restrict__ A,
                                              const float* __restrict__ gu,
                                              float* __restrict__ out) {
    int c = blockIdx.x;
    int tid = threadIdx.x;
    int d = tid & 255;
    int half = tid >> 8;
    __shared__ float sS[NB][NC];
    __shared__ float red[2][4][8];
    __shared__ int scnt[2][NC];

    // stage S[b][d] = sum over segments (cooperative, coalesced)
#pragma unroll
    for (int i = 0; i < 4; i++) {
        int e = tid + i * 512;
        int be = e >> 8, de = e & 255;
        float s = 0.f;
#pragma unroll
        for (int sg = 0; sg < KSEG; sg++) s += g_Sp[(sg * NB + be) * NC + de];
        sS[be][de] = s;
    }

    // prefetch G sums (16 independent loads)
    float Gv[4];
#pragma unroll
    for (int it = 0; it < 4; it++) {
        int b = half * 4 + it;
        float g = 0.f;
#pragma unroll
        for (int sg = 0; sg < KSEG; sg++)
            g += g_G[(size_t)(sg * NB + b) * NC * NC + c * NC + d];
        Gv[it] = g;
    }
    // prefetch gumbel pairs
    float2 u[4];
#pragma unroll
    for (int it = 0; it < 4; it++) {
        int b = half * 4 + it;
        u[it] = *(const float2*)(gu + ((size_t)(b * NC + c) * NC + d) * 2);
    }
    float Ad = A[d * (NC + 1)];
    float Ad2 = Ad * Ad;
    __syncthreads();

    float D[4];
#pragma unroll
    for (int it = 0; it < 4; it++) {
        int b = half * 4 + it;
        D[it] = Ad2 * (sS[b][c] + sS[b][d] - 2.f * Gv[it]) + 1e-10f;
        float m = (d == c) ? __int_as_float(0x7f800000) : D[it];
#pragma unroll
        for (int o = 16; o > 0; o >>= 1)
            m = fminf(m, __shfl_xor_sync(0xffffffffu, m, o));
        if ((d & 31) == 0) red[half][it][d >> 5] = m;
    }
    __syncthreads();

    const float RDIAG = 0.99f / (1.0f - 0.99f);
    int cnt = 0;
#pragma unroll
    for (int it = 0; it < 4; it++) {
        float Dmin = fminf(
            fminf(fminf(red[half][it][0], red[half][it][1]),
                  fminf(red[half][it][2], red[half][it][3])),
            fminf(fminf(red[half][it][4], red[half][it][5]),
                  fminf(red[half][it][6], red[half][it][7])));
        float r;
        if (d == c) {
            r = RDIAG;
        } else {
            float num = 0.99f * Dmin;
            r = num / (D[it] - num);
        }
        float r2 = r * r;

        float t0 = -__logf(u[it].x);
        float t1 = -__logf(u[it].y);
        float diff = r2 * t1 - t0;
        float thr = 1e-6f * (r2 * fmaxf(t1, 1.f) + fmaxf(t0, 1.f));
        bool take;
        if (fabsf(diff) > thr) {
            take = diff > 0.f;
        } else {
            float t0p = -logf(u[it].x);
            float t1p = -logf(u[it].y);
            take = r2 * t1p > t0p;
        }
        if (take) cnt++;
    }

    scnt[half][d] = cnt;
    __syncthreads();
    if (half == 0)
        out[c * NC + d] = (float)(scnt[0][d] + scnt[1][d]) * 0.125f;
}

// ---------------------------------------------------------------------------
extern "C" void kernel_launch(void* const* d_in, const int* in_sizes, int n_in,
                              void* d_out, int out_size) {
    const float* amp = (const float*)d_in[0];
    const float* ph  = (const float*)d_in[1];
    const float* A   = (const float*)d_in[2];
    const float* wa  = (const float*)d_in[3];
    const float* wp  = (const float*)d_in[4];
    const float* gu  = (const float*)d_in[5];
    float* out = (float*)d_out;

    k_gram<<<dim3(16, NB), 256>>>(amp, ph, wa, wp);
    k_mask<<<NC, 512>>>(A, gu, out);
}